// round 4
// baseline (speedup 1.0000x reference)
#include <cuda_runtime.h>
#include <cuda_bf16.h>

#define B_DIM 64
#define J_DIM 24
#define T_DIM 2048
#define T4 (T_DIM / 4)
#define LAMBDA_VEL 0.2
#define LAMBDA_FOOT 0.1
#define CONTACT_THRESH 0.05f

#define GRID_BLOCKS 1152   // 1152*256 = 294912 threads; n4/threads = 16 exactly; stride % T4 == 0
#define NTHREADS 256
#define MAIN_ITERS 16

// accumulators: [0]=recon, [1]=vel, [2]=foot_loss, [3]=cw_sum  (zero-init, reset by last block)
__device__ double g_acc[4];
__device__ unsigned int g_done;

__device__ __forceinline__ float sigmoidf_fast(float x) {
    return 1.0f / (1.0f + __expf(-x));
}

__global__ void __launch_bounds__(NTHREADS) k_fused(const float* __restrict__ pred,
                                                    const float* __restrict__ target,
                                                    const float* __restrict__ jp,
                                                    float* __restrict__ out) {
    const int tid = blockIdx.x * blockDim.x + threadIdx.x;
    const int stride = GRID_BLOCKS * NTHREADS;
    const int lane = threadIdx.x & 31;

    // ---------------- foot contact loss (first: loads overlap with main) ----------------
    float lsum = 0.0f, csum = 0.0f;
    {
        const int foot_map[4] = {7, 8, 10, 11};
        const int nfoot = B_DIM * 4 * T4;                 // 131072 < total threads
        if (tid < nfoot) {
            int c4 = tid & (T4 - 1);
            int row = tid >> 9;
            int b = row >> 2;
            int j = foot_map[row & 3];
            const float* base = jp + ((size_t)(b * J_DIM + j) * 3) * T_DIM;
            const float* xr = base;
            const float* yr = base + T_DIM;
            const float* zr = base + 2 * T_DIM;

            int col = c4 * 4;
            float4 x = ((const float4*)xr)[c4];
            float4 y = ((const float4*)yr)[c4];
            float4 z = ((const float4*)zr)[c4];
            bool has_next = (col + 4 < T_DIM);
            float xs[5] = {x.x, x.y, x.z, x.w, has_next ? xr[col + 4] : 0.0f};
            float ys[5] = {y.x, y.y, y.z, y.w, has_next ? yr[col + 4] : 0.0f};
            float zs[5] = {z.x, z.y, z.z, z.w, has_next ? zr[col + 4] : 0.0f};

            int kmax = has_next ? 4 : 3;
            #pragma unroll
            for (int k = 0; k < 4; k++) {
                if (k < kmax) {
                    float w0 = sigmoidf_fast((CONTACT_THRESH - ys[k])     * 20.0f);
                    float w1 = sigmoidf_fast((CONTACT_THRESH - ys[k + 1]) * 20.0f);
                    float cw = 0.5f * (w0 + w1);
                    float dx = xs[k + 1] - xs[k];
                    float dz = zs[k + 1] - zs[k];
                    lsum += (dx * dx + dz * dz) * cw;
                    csum += cw;
                }
            }
        }
    }

    // ---------------- main: recon + vel over pred/target ----------------
    // stride % T4 == 0  ->  (i mod T4) is constant across iterations:
    const bool valid = (tid & (T4 - 1)) != (T4 - 1);   // not the last float4 of a T-row
    const bool edge  = valid && (lane == 31);          // lane-31 needs a scalar neighbor load

    float recon = 0.0f, vel = 0.0f;
    {
        const float4* p4 = (const float4*)pred;
        const float4* t4 = (const float4*)target;

        #pragma unroll
        for (int c = 0; c < MAIN_ITERS; c += 4) {
            int i0 = tid + c * stride;
            int i1 = i0 + stride;
            int i2 = i1 + stride;
            int i3 = i2 + stride;
            // front-batched loads (8 x LDG.128)
            float4 P0 = p4[i0], P1 = p4[i1], P2 = p4[i2], P3 = p4[i3];
            float4 T0 = t4[i0], T1 = t4[i1], T2 = t4[i2], T3 = t4[i3];
            // lane-31 boundary neighbors (2 scalar loads each, L1/L2 hits)
            float n0 = 0, n1 = 0, n2 = 0, n3 = 0;
            if (edge) {
                n0 = pred[i0 * 4 + 4] - target[i0 * 4 + 4];
                n1 = pred[i1 * 4 + 4] - target[i1 * 4 + 4];
                n2 = pred[i2 * 4 + 4] - target[i2 * 4 + 4];
                n3 = pred[i3 * 4 + 4] - target[i3 * 4 + 4];
            }

            #pragma unroll
            for (int u = 0; u < 4; u++) {
                float4 p = (u == 0) ? P0 : (u == 1) ? P1 : (u == 2) ? P2 : P3;
                float4 t = (u == 0) ? T0 : (u == 1) ? T1 : (u == 2) ? T2 : T3;
                float nb = (u == 0) ? n0 : (u == 1) ? n1 : (u == 2) ? n2 : n3;
                float d0 = p.x - t.x, d1 = p.y - t.y, d2 = p.z - t.z, d3 = p.w - t.w;
                recon += d0 * d0 + d1 * d1 + d2 * d2 + d3 * d3;
                float v01 = d1 - d0, v12 = d2 - d1, v23 = d3 - d2;
                float v = v01 * v01 + v12 * v12 + v23 * v23;
                float dn = __shfl_down_sync(0xFFFFFFFFu, d0, 1);   // lane l+1's d0 = our t+4
                if (lane == 31) dn = nb;
                if (valid) {
                    float v3n = dn - d3;
                    v += v3n * v3n;
                }
                vel += v;
            }
        }
    }

    // ---------------- block reduction ----------------
    __shared__ float s0[8], s1[8], s2[8], s3[8];
    #pragma unroll
    for (int o = 16; o; o >>= 1) {
        recon += __shfl_down_sync(0xFFFFFFFFu, recon, o);
        vel   += __shfl_down_sync(0xFFFFFFFFu, vel, o);
        lsum  += __shfl_down_sync(0xFFFFFFFFu, lsum, o);
        csum  += __shfl_down_sync(0xFFFFFFFFu, csum, o);
    }
    int warp = threadIdx.x >> 5;
    if ((threadIdx.x & 31) == 0) {
        s0[warp] = recon; s1[warp] = vel; s2[warp] = lsum; s3[warp] = csum;
    }
    __syncthreads();
    if (threadIdx.x == 0) {
        float r = 0, v = 0, l = 0, c = 0;
        #pragma unroll
        for (int w = 0; w < NTHREADS / 32; w++) { r += s0[w]; v += s1[w]; l += s2[w]; c += s3[w]; }
        atomicAdd(&g_acc[0], (double)r);
        atomicAdd(&g_acc[1], (double)v);
        atomicAdd(&g_acc[2], (double)l);
        atomicAdd(&g_acc[3], (double)c);
        __threadfence();
        unsigned int done = atomicAdd(&g_done, 1u);
        if (done == gridDim.x - 1) {
            const double N1 = (double)B_DIM * J_DIM * 6 * T_DIM;
            const double N2 = (double)B_DIM * J_DIM * 6 * (T_DIM - 1);
            double recon_m = g_acc[0] / N1;
            double vel_m   = g_acc[1] / N2;
            double foot_m  = g_acc[2] / (g_acc[3] + 1e-08);
            out[0] = (float)(recon_m + LAMBDA_VEL * vel_m + LAMBDA_FOOT * foot_m);
            g_acc[0] = 0.0; g_acc[1] = 0.0; g_acc[2] = 0.0; g_acc[3] = 0.0;
            g_done = 0u;
        }
    }
}

extern "C" void kernel_launch(void* const* d_in, const int* in_sizes, int n_in,
                              void* d_out, int out_size) {
    const float* pred   = (const float*)d_in[0];
    const float* target = (const float*)d_in[1];
    const float* jp     = (const float*)d_in[2];
    float* out = (float*)d_out;
    k_fused<<<GRID_BLOCKS, NTHREADS>>>(pred, target, jp, out);
}

// round 5
// speedup vs baseline: 1.1242x; 1.1242x over previous
#include <cuda_runtime.h>
#include <cuda_bf16.h>

#define B_DIM 64
#define J_DIM 24
#define T_DIM 2048
#define T4 (T_DIM / 4)
#define LAMBDA_VEL 0.2
#define LAMBDA_FOOT 0.1
#define CONTACT_THRESH 0.05f

#define GRID_BLOCKS 1184   // 148 SMs * 8 resident blocks -> perfectly balanced single wave
#define NTHREADS 256
// stride = 1184*256 = 303104; 303104 % 512 == 0 -> (i mod T4) invariant per thread

// accumulators: [0]=recon, [1]=vel, [2]=foot_loss, [3]=cw_sum  (zero-init, reset by last block)
__device__ double g_acc[4];
__device__ unsigned int g_done;

__device__ __forceinline__ float sigmoidf_fast(float x) {
    return 1.0f / (1.0f + __expf(-x));
}

__global__ void __launch_bounds__(NTHREADS) k_fused(const float* __restrict__ pred,
                                                    const float* __restrict__ target,
                                                    const float* __restrict__ jp,
                                                    float* __restrict__ out) {
    const int tid = blockIdx.x * blockDim.x + threadIdx.x;
    const int stride = GRID_BLOCKS * NTHREADS;
    const int lane = threadIdx.x & 31;

    // ---------------- main: recon + vel over pred/target ----------------
    // stride % T4 == 0 -> these are loop-invariant per thread:
    const bool valid = (tid & (T4 - 1)) != (T4 - 1);   // not the last float4 of a T-row
    const bool edge  = valid && (lane == 31);          // lane 31 needs scalar neighbor loads

    float recon = 0.0f, vel = 0.0f;
    {
        const int n4 = (B_DIM * J_DIM * 6 * T_DIM) / 4;   // 4,718,592
        const float4* p4 = (const float4*)pred;
        const float4* t4 = (const float4*)target;

        int i = tid;
        #pragma unroll 2
        for (; i < n4; i += stride) {
            float4 p = __ldcs(p4 + i);
            float4 t = __ldcs(t4 + i);
            float d0 = p.x - t.x, d1 = p.y - t.y, d2 = p.z - t.z, d3 = p.w - t.w;
            recon += d0 * d0 + d1 * d1 + d2 * d2 + d3 * d3;
            float v01 = d1 - d0, v12 = d2 - d1, v23 = d3 - d2;
            float v = v01 * v01 + v12 * v12 + v23 * v23;
            float dn = __shfl_down_sync(0xFFFFFFFFu, d0, 1);   // lane l+1's d0 = our t+4
            if (edge) {
                int e = i * 4 + 4;
                dn = pred[e] - target[e];                      // L1/L2 hit
            }
            if (valid) {
                float v3n = dn - d3;
                v += v3n * v3n;
            }
            vel += v;
        }
    }

    // ---------------- foot contact loss ----------------
    float lsum = 0.0f, csum = 0.0f;
    {
        const int foot_map[4] = {7, 8, 10, 11};
        const int nfoot = B_DIM * 4 * T4;                 // 131072 < total threads
        if (tid < nfoot) {
            int c4 = tid & (T4 - 1);
            int row = tid >> 9;
            int b = row >> 2;
            int j = foot_map[row & 3];
            const float* base = jp + ((size_t)(b * J_DIM + j) * 3) * T_DIM;
            const float* xr = base;
            const float* yr = base + T_DIM;
            const float* zr = base + 2 * T_DIM;

            int col = c4 * 4;
            float4 x = ((const float4*)xr)[c4];
            float4 y = ((const float4*)yr)[c4];
            float4 z = ((const float4*)zr)[c4];
            bool has_next = (col + 4 < T_DIM);
            float xs[5] = {x.x, x.y, x.z, x.w, has_next ? xr[col + 4] : 0.0f};
            float ys[5] = {y.x, y.y, y.z, y.w, has_next ? yr[col + 4] : 0.0f};
            float zs[5] = {z.x, z.y, z.z, z.w, has_next ? zr[col + 4] : 0.0f};

            int kmax = has_next ? 4 : 3;
            #pragma unroll
            for (int k = 0; k < 4; k++) {
                if (k < kmax) {
                    float w0 = sigmoidf_fast((CONTACT_THRESH - ys[k])     * 20.0f);
                    float w1 = sigmoidf_fast((CONTACT_THRESH - ys[k + 1]) * 20.0f);
                    float cw = 0.5f * (w0 + w1);
                    float dx = xs[k + 1] - xs[k];
                    float dz = zs[k + 1] - zs[k];
                    lsum += (dx * dx + dz * dz) * cw;
                    csum += cw;
                }
            }
        }
    }

    // ---------------- block reduction ----------------
    __shared__ float s0[8], s1[8], s2[8], s3[8];
    #pragma unroll
    for (int o = 16; o; o >>= 1) {
        recon += __shfl_down_sync(0xFFFFFFFFu, recon, o);
        vel   += __shfl_down_sync(0xFFFFFFFFu, vel, o);
        lsum  += __shfl_down_sync(0xFFFFFFFFu, lsum, o);
        csum  += __shfl_down_sync(0xFFFFFFFFu, csum, o);
    }
    int warp = threadIdx.x >> 5;
    if ((threadIdx.x & 31) == 0) {
        s0[warp] = recon; s1[warp] = vel; s2[warp] = lsum; s3[warp] = csum;
    }
    __syncthreads();
    if (threadIdx.x == 0) {
        float r = 0, v = 0, l = 0, c = 0;
        #pragma unroll
        for (int w = 0; w < NTHREADS / 32; w++) { r += s0[w]; v += s1[w]; l += s2[w]; c += s3[w]; }
        atomicAdd(&g_acc[0], (double)r);
        atomicAdd(&g_acc[1], (double)v);
        atomicAdd(&g_acc[2], (double)l);
        atomicAdd(&g_acc[3], (double)c);
        __threadfence();
        unsigned int done = atomicAdd(&g_done, 1u);
        if (done == gridDim.x - 1) {
            const double N1 = (double)B_DIM * J_DIM * 6 * T_DIM;
            const double N2 = (double)B_DIM * J_DIM * 6 * (T_DIM - 1);
            double recon_m = g_acc[0] / N1;
            double vel_m   = g_acc[1] / N2;
            double foot_m  = g_acc[2] / (g_acc[3] + 1e-08);
            out[0] = (float)(recon_m + LAMBDA_VEL * vel_m + LAMBDA_FOOT * foot_m);
            g_acc[0] = 0.0; g_acc[1] = 0.0; g_acc[2] = 0.0; g_acc[3] = 0.0;
            g_done = 0u;
        }
    }
}

extern "C" void kernel_launch(void* const* d_in, const int* in_sizes, int n_in,
                              void* d_out, int out_size) {
    const float* pred   = (const float*)d_in[0];
    const float* target = (const float*)d_in[1];
    const float* jp     = (const float*)d_in[2];
    float* out = (float*)d_out;
    k_fused<<<GRID_BLOCKS, NTHREADS>>>(pred, target, jp, out);
}